// round 12
// baseline (speedup 1.0000x reference)
#include <cuda_runtime.h>

#define TH 16
#define TW 64
#define NT 256
#define HIMG 512
#define WIMG 512
#define SAW 68   // padded row stride for s_a
#define SCW 36   // padded row stride for s_c

__constant__ float c_D[64];   // DCT matrix, row-major

__device__ __forceinline__ float dot8c(const float* x, int l) {
    const float4 d0 = *(const float4*)&c_D[l*8];
    const float4 d1 = *(const float4*)&c_D[l*8 + 4];
    return fmaf(x[7], d1.w, fmaf(x[6], d1.z, fmaf(x[5], d1.y,
           fmaf(x[4], d1.x, fmaf(x[3], d0.w, fmaf(x[2], d0.z,
           fmaf(x[1], d0.y, x[0] * d0.x)))))));
}
__device__ __forceinline__ float dot4e(const float* x, int l) {
    const float4 d0 = *(const float4*)&c_D[l*8];
    const float4 d1 = *(const float4*)&c_D[l*8 + 4];
    float e0 = d0.x + d0.y, e1 = d0.z + d0.w;
    float e2 = d1.x + d1.y, e3 = d1.z + d1.w;
    return fmaf(x[3], e3, fmaf(x[2], e2, fmaf(x[1], e1, x[0] * e0)));
}
__device__ __forceinline__ void accum8(const float* y, float* g) {
    #pragma unroll
    for (int l = 0; l < 8; l++) g[l] = 0.0f;
    #pragma unroll
    for (int k = 0; k < 8; k++) {
        const float4 d0 = *(const float4*)&c_D[k*8];
        const float4 d1 = *(const float4*)&c_D[k*8 + 4];
        const float t = y[k];
        g[0]=fmaf(t,d0.x,g[0]); g[1]=fmaf(t,d0.y,g[1]); g[2]=fmaf(t,d0.z,g[2]); g[3]=fmaf(t,d0.w,g[3]);
        g[4]=fmaf(t,d1.x,g[4]); g[5]=fmaf(t,d1.y,g[5]); g[6]=fmaf(t,d1.z,g[6]); g[7]=fmaf(t,d1.w,g[7]);
    }
}
__device__ __forceinline__ void quant8(float* y, const float* qr, const float* rr) {
    const float4 q0 = *(const float4*)&qr[0];
    const float4 q1 = *(const float4*)&qr[4];
    const float4 r0 = *(const float4*)&rr[0];
    const float4 r1 = *(const float4*)&rr[4];
    y[0]=rintf(rintf(y[0]*r0.x)*q0.x); y[1]=rintf(rintf(y[1]*r0.y)*q0.y);
    y[2]=rintf(rintf(y[2]*r0.z)*q0.z); y[3]=rintf(rintf(y[3]*r0.w)*q0.w);
    y[4]=rintf(rintf(y[4]*r1.x)*q1.x); y[5]=rintf(rintf(y[5]*r1.y)*q1.y);
    y[6]=rintf(rintf(y[6]*r1.z)*q1.z); y[7]=rintf(rintf(y[7]*r1.w)*q1.w);
}

// 8x8 transpose among 4 consecutive lanes; thread t holds rows {2t,2t+1} in (Ta,Tb),
// receives columns {2t,2t+1} in (Ca,Cb). b0 = t&1, b1 = (t>>1)&1.
__device__ __forceinline__ void trans8(const float* Ta, const float* Tb,
                                       float* Ca, float* Cb, bool b0, bool b1) {
    const unsigned M = 0xffffffffu;
    float e0 = b0 ? Ta[0] : Ta[2];  float e1 = b0 ? Ta[1] : Ta[3];
    float e2 = b0 ? Tb[0] : Tb[2];  float e3 = b0 ? Tb[1] : Tb[3];
    float e4 = b0 ? Ta[4] : Ta[6];  float e5 = b0 ? Ta[5] : Ta[7];
    float e6 = b0 ? Tb[4] : Tb[6];  float e7 = b0 ? Tb[5] : Tb[7];
    e0 = __shfl_xor_sync(M, e0, 1); e1 = __shfl_xor_sync(M, e1, 1);
    e2 = __shfl_xor_sync(M, e2, 1); e3 = __shfl_xor_sync(M, e3, 1);
    e4 = __shfl_xor_sync(M, e4, 1); e5 = __shfl_xor_sync(M, e5, 1);
    e6 = __shfl_xor_sync(M, e6, 1); e7 = __shfl_xor_sync(M, e7, 1);
    float U00 = b0 ? e0 : Ta[0], U01 = b0 ? e1 : Ta[1], U02 = b0 ? e4 : Ta[4], U03 = b0 ? e5 : Ta[5];
    float U10 = b0 ? e2 : Tb[0], U11 = b0 ? e3 : Tb[1], U12 = b0 ? e6 : Tb[4], U13 = b0 ? e7 : Tb[5];
    float U20 = b0 ? Ta[2] : e0, U21 = b0 ? Ta[3] : e1, U22 = b0 ? Ta[6] : e4, U23 = b0 ? Ta[7] : e5;
    float U30 = b0 ? Tb[2] : e2, U31 = b0 ? Tb[3] : e3, U32 = b0 ? Tb[6] : e6, U33 = b0 ? Tb[7] : e7;
    float f0 = b1 ? U00 : U02;  float f1 = b1 ? U01 : U03;
    float f2 = b1 ? U10 : U12;  float f3 = b1 ? U11 : U13;
    float f4 = b1 ? U20 : U22;  float f5 = b1 ? U21 : U23;
    float f6 = b1 ? U30 : U32;  float f7 = b1 ? U31 : U33;
    f0 = __shfl_xor_sync(M, f0, 2); f1 = __shfl_xor_sync(M, f1, 2);
    f2 = __shfl_xor_sync(M, f2, 2); f3 = __shfl_xor_sync(M, f3, 2);
    f4 = __shfl_xor_sync(M, f4, 2); f5 = __shfl_xor_sync(M, f5, 2);
    f6 = __shfl_xor_sync(M, f6, 2); f7 = __shfl_xor_sync(M, f7, 2);
    Ca[0] = b1 ? f0 : U00;  Ca[1] = b1 ? f2 : U10;  Ca[2] = b1 ? f4 : U20;  Ca[3] = b1 ? f6 : U30;
    Ca[4] = b1 ? U02 : f0;  Ca[5] = b1 ? U12 : f2;  Ca[6] = b1 ? U22 : f4;  Ca[7] = b1 ? U32 : f6;
    Cb[0] = b1 ? f1 : U01;  Cb[1] = b1 ? f3 : U11;  Cb[2] = b1 ? f5 : U21;  Cb[3] = b1 ? f7 : U31;
    Cb[4] = b1 ? U03 : f1;  Cb[5] = b1 ? U13 : f3;  Cb[6] = b1 ? U23 : f5;  Cb[7] = b1 ? U33 : f7;
}

// 4x8 transpose among 4 lanes; thread t holds row t (Ta[8]); gets cols {2t,2t+1} in Pa[4],Pb[4].
__device__ __forceinline__ void trans4x8(const float* Ta, float* Pa, float* Pb, bool b0, bool b1) {
    const unsigned M = 0xffffffffu;
    float e0 = b0 ? Ta[0] : Ta[2];  float e1 = b0 ? Ta[1] : Ta[3];
    float e2 = b0 ? Ta[4] : Ta[6];  float e3 = b0 ? Ta[5] : Ta[7];
    e0 = __shfl_xor_sync(M, e0, 1); e1 = __shfl_xor_sync(M, e1, 1);
    e2 = __shfl_xor_sync(M, e2, 1); e3 = __shfl_xor_sync(M, e3, 1);
    float U00 = b0 ? e0 : Ta[0], U01 = b0 ? e1 : Ta[1], U02 = b0 ? e2 : Ta[4], U03 = b0 ? e3 : Ta[5];
    float U10 = b0 ? Ta[2] : e0, U11 = b0 ? Ta[3] : e1, U12 = b0 ? Ta[6] : e2, U13 = b0 ? Ta[7] : e3;
    float f0 = b1 ? U00 : U02;  float f1 = b1 ? U01 : U03;
    float f2 = b1 ? U10 : U12;  float f3 = b1 ? U11 : U13;
    f0 = __shfl_xor_sync(M, f0, 2); f1 = __shfl_xor_sync(M, f1, 2);
    f2 = __shfl_xor_sync(M, f2, 2); f3 = __shfl_xor_sync(M, f3, 2);
    Pa[0] = b1 ? f0 : U00;  Pa[1] = b1 ? f2 : U10;  Pa[2] = b1 ? U02 : f0;  Pa[3] = b1 ? U12 : f2;
    Pb[0] = b1 ? f1 : U01;  Pb[1] = b1 ? f3 : U11;  Pb[2] = b1 ? U03 : f1;  Pb[3] = b1 ? U13 : f3;
}

__global__ __launch_bounds__(NT, 4) void jpeg_kernel(
    const float* __restrict__ in, const float* __restrict__ quant,
    const float* __restrict__ dct, float* __restrict__ out)
{
    __shared__ __align__(16) float s_a[3][TH][SAW];   // X(y) -> Z(all)
    __shared__ __align__(16) float s_c[2][TH/2][SCW]; // half-res chroma
    __shared__ __align__(16) float s_qt[3][8][8];     // q transposed
    __shared__ __align__(16) float s_rqt[3][8][8];    // 1/q transposed

    const int tid = threadIdx.x;
    const int b   = blockIdx.z;
    const int ty0 = blockIdx.y * TH;
    const int tx0 = blockIdx.x * TW;

    if (tid < 192) {
        int i = tid;
        float qv = rintf(quant[i] * 255.0f);
        float q1 = rintf((qv * 50.0f + 50.0f) / 100.0f);
        float q  = fminf(fmaxf(q1, 1.0f), 255.0f);
        int ci = i >> 6, ri = (i >> 3) & 7, li = i & 7;
        s_qt[ci][li][ri]  = q;
        s_rqt[ci][li][ri] = 1.0f / q;
    }

    const size_t plane = (size_t)HIMG * WIMG;
    const float* base  = in  + (size_t)b * 3 * plane;
    float*       obase = out + (size_t)b * 3 * plane;

    // ---- phase 1: 4x1 strips (LDG.128); chroma 2x2 mean via in-warp shuffle ----
    {
        const int sy = tid >> 4;
        const int sx = tid & 15;
        const int px = sx * 4;
        const size_t idx = (size_t)(ty0 + sy) * WIMG + (tx0 + px);

        const float4 r4 = *(const float4*)&base[idx];
        const float4 g4 = *(const float4*)&base[plane + idx];
        const float4 b4 = *(const float4*)&base[2*plane + idx];

        float R[4] = {255.0f*r4.x, 255.0f*r4.y, 255.0f*r4.z, 255.0f*r4.w};
        float G[4] = {255.0f*g4.x, 255.0f*g4.y, 255.0f*g4.z, 255.0f*g4.w};
        float B[4] = {255.0f*b4.x, 255.0f*b4.y, 255.0f*b4.z, 255.0f*b4.w};

        #define YV(R_,G_,B_)  fmaf(0.114f,(B_), fmaf(0.587f,(G_), 0.299f*(R_)))
        #define CBV(R_,G_,B_) (fmaf(0.5f,(B_),  fmaf(-0.331264108f,(G_), -0.168735892f*(R_))) + 128.0f)
        #define CRV(R_,G_,B_) (fmaf(-0.081312411f,(B_), fmaf(-0.418687589f,(G_), 0.5f*(R_))) + 128.0f)
        #define CL(v) fminf(fmaxf((v), 0.0f), 255.0f)

        float Y[4], CB[4], CR[4];
        #pragma unroll
        for (int e = 0; e < 4; e++) {
            Y[e]  = CL(YV(R[e], G[e], B[e])) - 128.0f;
            CB[e] = CL(CBV(R[e], G[e], B[e]));
            CR[e] = CL(CRV(R[e], G[e], B[e]));
        }
        *(float4*)&s_a[0][sy][px] = make_float4(Y[0], Y[1], Y[2], Y[3]);

        float pcb0 = __shfl_xor_sync(0xffffffffu, CB[0], 16);
        float pcb1 = __shfl_xor_sync(0xffffffffu, CB[1], 16);
        float pcb2 = __shfl_xor_sync(0xffffffffu, CB[2], 16);
        float pcb3 = __shfl_xor_sync(0xffffffffu, CB[3], 16);
        float pcr0 = __shfl_xor_sync(0xffffffffu, CR[0], 16);
        float pcr1 = __shfl_xor_sync(0xffffffffu, CR[1], 16);
        float pcr2 = __shfl_xor_sync(0xffffffffu, CR[2], 16);
        float pcr3 = __shfl_xor_sync(0xffffffffu, CR[3], 16);
        if ((sy & 1) == 0) {
            float cbm0 = 0.25f * (((CB[0] + CB[1]) + pcb0) + pcb1) - 128.0f;
            float cbm1 = 0.25f * (((CB[2] + CB[3]) + pcb2) + pcb3) - 128.0f;
            float crm0 = 0.25f * (((CR[0] + CR[1]) + pcr0) + pcr1) - 128.0f;
            float crm1 = 0.25f * (((CR[2] + CR[3]) + pcr2) + pcr3) - 128.0f;
            *(float2*)&s_c[0][sy >> 1][sx*2] = make_float2(cbm0, cbm1);
            *(float2*)&s_c[1][sy >> 1][sx*2] = make_float2(crm0, crm1);
        }
    }
    __syncthreads();

    // ---- DCT chain, fully register-resident per quad; 48 units * 4 threads ----
    if (tid < 192) {
        const int unit = tid >> 2;
        const int t    = tid & 3;
        const bool b0  = t & 1;
        const bool b1  = (t >> 1) & 1;
        int c, by, bx;
        if (unit < 16) { c = 0; by = unit >> 3; bx = unit & 7; }
        else { int u = unit - 16; c = 1 + (u >> 4); int rem = u & 15; by = rem >> 3; bx = rem & 7; }
        const int ra = 2 * t, rb = 2 * t + 1;
        float* pW = &s_a[c][by*8][bx*8];

        float Ya[8], Yb[8];       // F^T rows ra, rb (then quantized)
        if (c == 0) {
            float Xa[8], Xb[8];
            *(float4*)&Xa[0] = *(const float4*)(pW + ra*SAW);
            *(float4*)&Xa[4] = *(const float4*)(pW + ra*SAW + 4);
            *(float4*)&Xb[0] = *(const float4*)(pW + rb*SAW);
            *(float4*)&Xb[4] = *(const float4*)(pW + rb*SAW + 4);
            float Ta[8], Tb[8];   // T1 = X*D^T rows
            #pragma unroll
            for (int l = 0; l < 8; l++) { Ta[l] = dot8c(Xa, l); Tb[l] = dot8c(Xb, l); }
            float Ca[8], Cb[8];   // T1^T rows ra, rb
            trans8(Ta, Tb, Ca, Cb, b0, b1);
            #pragma unroll
            for (int l = 0; l < 8; l++) { Ya[l] = dot8c(Ca, l); Yb[l] = dot8c(Cb, l); }
        } else {
            const int cc = c - 1;
            float Xh[4];
            *(float4*)&Xh[0] = *(const float4*)(&s_c[cc][by*4 + t][bx*4]);
            float Tc[8];          // T1c row t = Xh * E^T
            #pragma unroll
            for (int l = 0; l < 8; l++) Tc[l] = dot4e(Xh, l);
            float Pa[4], Pb[4];   // T1c^T rows ra, rb
            trans4x8(Tc, Pa, Pb, b0, b1);
            #pragma unroll
            for (int l = 0; l < 8; l++) { Ya[l] = dot4e(Pa, l); Yb[l] = dot4e(Pb, l); }
        }
        quant8(Ya, &s_qt[c][ra][0], &s_rqt[c][ra][0]);
        quant8(Yb, &s_qt[c][rb][0], &s_rqt[c][rb][0]);

        // W^T rows = Y2'^T * D
        float Ga[8], Gb[8];
        accum8(Ya, Ga);
        accum8(Yb, Gb);
        // W rows ra, rb
        float Wa[8], Wb[8];
        trans8(Ga, Gb, Wa, Wb, b0, b1);
        // Z rows = W * D + off
        float Za[8], Zb[8];
        accum8(Wa, Za);
        accum8(Wb, Zb);
        const float off = (c == 0) ? 128.0f : 0.0f;
        #pragma unroll
        for (int l = 0; l < 8; l++) { Za[l] += off; Zb[l] += off; }

        *(float4*)(pW + ra*SAW)     = make_float4(Za[0], Za[1], Za[2], Za[3]);
        *(float4*)(pW + ra*SAW + 4) = make_float4(Za[4], Za[5], Za[6], Za[7]);
        *(float4*)(pW + rb*SAW)     = make_float4(Zb[0], Zb[1], Zb[2], Zb[3]);
        *(float4*)(pW + rb*SAW + 4) = make_float4(Zb[4], Zb[5], Zb[6], Zb[7]);
    }
    __syncthreads();

    // ---- phase 5: YCbCr -> RGB, clip, round, store ----
    {
        const int py  = tid >> 4;
        const int px4 = (tid & 15) * 4;
        const float4 yv  = *(const float4*)&s_a[0][py][px4];
        const float4 cbv = *(const float4*)&s_a[1][py][px4];
        const float4 crv = *(const float4*)&s_a[2][py][px4];

        #define FIN(v) (rintf(fminf(fmaxf((v), 0.0f), 255.0f)) * (1.0f/255.0f))
        float4 R, G, Bv;
        R.x = FIN(fmaf(1.402f, crv.x, yv.x));  R.y = FIN(fmaf(1.402f, crv.y, yv.y));
        R.z = FIN(fmaf(1.402f, crv.z, yv.z));  R.w = FIN(fmaf(1.402f, crv.w, yv.w));
        G.x = FIN(fmaf(-0.714136286f, crv.x, fmaf(-0.344136286f, cbv.x, yv.x)));
        G.y = FIN(fmaf(-0.714136286f, crv.y, fmaf(-0.344136286f, cbv.y, yv.y)));
        G.z = FIN(fmaf(-0.714136286f, crv.z, fmaf(-0.344136286f, cbv.z, yv.z)));
        G.w = FIN(fmaf(-0.714136286f, crv.w, fmaf(-0.344136286f, cbv.w, yv.w)));
        Bv.x = FIN(fmaf(1.772f, cbv.x, yv.x)); Bv.y = FIN(fmaf(1.772f, cbv.y, yv.y));
        Bv.z = FIN(fmaf(1.772f, cbv.z, yv.z)); Bv.w = FIN(fmaf(1.772f, cbv.w, yv.w));

        const size_t idx = (size_t)(ty0 + py) * WIMG + (tx0 + px4);
        *(float4*)&obase[idx]           = R;
        *(float4*)&obase[plane + idx]   = G;
        *(float4*)&obase[2*plane + idx] = Bv;
    }
}

extern "C" void kernel_launch(void* const* d_in, const int* in_sizes, int n_in,
                              void* d_out, int out_size)
{
    const float* x = nullptr;
    const float* q = nullptr;
    const float* d = nullptr;
    int nimg = 0;
    for (int i = 0; i < n_in; i++) {
        if (in_sizes[i] == 192)      q = (const float*)d_in[i];
        else if (in_sizes[i] == 64)  d = (const float*)d_in[i];
        else { x = (const float*)d_in[i]; nimg = in_sizes[i] / (3 * HIMG * WIMG); }
    }
    cudaMemcpyToSymbolAsync(c_D, d, 64 * sizeof(float), 0,
                            cudaMemcpyDeviceToDevice, 0);
    dim3 grid(WIMG / TW, HIMG / TH, nimg);
    jpeg_kernel<<<grid, NT>>>(x, q, d, (float*)d_out);
}

// round 13
// speedup vs baseline: 1.5032x; 1.5032x over previous
#include <cuda_runtime.h>

#define TH 16
#define TW 64
#define NT 256
#define HIMG 512
#define WIMG 512
#define SAW 68
#define SCW 36

__constant__ float c_D[64];

__device__ __forceinline__ float dot8c(const float* x, int l) {
    const float4 d0 = *(const float4*)&c_D[l*8];
    const float4 d1 = *(const float4*)&c_D[l*8 + 4];
    return fmaf(x[7], d1.w, fmaf(x[6], d1.z, fmaf(x[5], d1.y,
           fmaf(x[4], d1.x, fmaf(x[3], d0.w, fmaf(x[2], d0.z,
           fmaf(x[1], d0.y, x[0] * d0.x)))))));
}

__global__ __launch_bounds__(NT, 4) void jpeg_kernel(
    const float* __restrict__ in, const float* __restrict__ quant,
    const float* __restrict__ dct, float* __restrict__ out)
{
    __shared__ __align__(16) float s_a[3][TH][SAW];   // A' / V / Z
    __shared__ __align__(16) float s_c[2][TH/2][SCW]; // half-res chroma
    __shared__ __align__(16) float s_d[8][8];
    __shared__ __align__(16) float s_dt[8][8];
    __shared__ __align__(16) float s_e[8][4];
    __shared__ __align__(16) float s_q[3][8][8];
    __shared__ __align__(16) float s_rq[3][8][8];

    const int tid = threadIdx.x;
    const int b   = blockIdx.z;
    const int ty0 = blockIdx.y * TH;
    const int tx0 = blockIdx.x * TW;

    // ---- tables (verbatim round 8) ----
    if (tid < 64) {
        float v = dct[tid];
        int i = tid >> 3, j = tid & 7;
        s_d[i][j]  = v;
        s_dt[j][i] = v;
    }
    if (tid < 32) {
        int i = tid >> 2, h = tid & 3;
        s_e[i][h] = dct[i * 8 + 2 * h] + dct[i * 8 + 2 * h + 1];
    }
    if (tid >= 64 && tid < 256) {
        int i = tid - 64;
        float qv = rintf(quant[i] * 255.0f);
        float q1 = rintf((qv * 50.0f + 50.0f) / 100.0f);
        float q  = fminf(fmaxf(q1, 1.0f), 255.0f);
        int ci = i >> 6, ri = (i >> 3) & 7, li = i & 7;
        s_q[ci][ri][li]  = q;
        s_rq[ci][ri][li] = 1.0f / q;
    }

    const size_t plane = (size_t)HIMG * WIMG;
    const float* base  = in  + (size_t)b * 3 * plane;
    float*       obase = out + (size_t)b * 3 * plane;

    // ---- phase 1 (fused with luma stage A): 64 luma threads own 2 adjacent
    //      rows of one 8x8 luma block; compute YCbCr, T1 rows, chroma means ----
    #define YV(R_,G_,B_)  fmaf(0.114f,(B_), fmaf(0.587f,(G_), 0.299f*(R_)))
    #define CBV(R_,G_,B_) (fmaf(0.5f,(B_),  fmaf(-0.331264108f,(G_), -0.168735892f*(R_))) + 128.0f)
    #define CRV(R_,G_,B_) (fmaf(-0.081312411f,(B_), fmaf(-0.418687589f,(G_), 0.5f*(R_))) + 128.0f)
    #define CL(v) fminf(fmaxf((v), 0.0f), 255.0f)

    if (tid < 64) {
        const int u   = tid >> 2;         // luma block 0..15
        const int t   = tid & 3;
        const int by_ = u >> 3, bx_ = u & 7;
        const int gy  = ty0 + by_*8 + 2*t;
        const int gx  = tx0 + bx_*8;
        float* pA = &s_a[0][by_*8][bx_*8];

        float CBa[8], CRa[8], CBb[8], CRb[8];

        #define LROW(RR, CBo, CRo) { \
            const size_t idx = (size_t)(gy + (RR)) * WIMG + gx; \
            const float4 rA = *(const float4*)&base[idx]; \
            const float4 rB = *(const float4*)&base[idx + 4]; \
            const float4 gA = *(const float4*)&base[plane + idx]; \
            const float4 gB = *(const float4*)&base[plane + idx + 4]; \
            const float4 bA = *(const float4*)&base[2*plane + idx]; \
            const float4 bB = *(const float4*)&base[2*plane + idx + 4]; \
            float Rr[8] = {255.0f*rA.x,255.0f*rA.y,255.0f*rA.z,255.0f*rA.w, \
                           255.0f*rB.x,255.0f*rB.y,255.0f*rB.z,255.0f*rB.w}; \
            float Gr[8] = {255.0f*gA.x,255.0f*gA.y,255.0f*gA.z,255.0f*gA.w, \
                           255.0f*gB.x,255.0f*gB.y,255.0f*gB.z,255.0f*gB.w}; \
            float Br[8] = {255.0f*bA.x,255.0f*bA.y,255.0f*bA.z,255.0f*bA.w, \
                           255.0f*bB.x,255.0f*bB.y,255.0f*bB.z,255.0f*bB.w}; \
            float Yv[8]; \
            _Pragma("unroll") \
            for (int e = 0; e < 8; e++) { \
                Yv[e]  = CL(YV(Rr[e], Gr[e], Br[e])) - 128.0f; \
                CBo[e] = CL(CBV(Rr[e], Gr[e], Br[e])); \
                CRo[e] = CL(CRV(Rr[e], Gr[e], Br[e])); \
            } \
            float T1[8]; \
            _Pragma("unroll") \
            for (int l = 0; l < 8; l++) T1[l] = dot8c(Yv, l); \
            *(float4*)(pA + (2*t + (RR))*SAW)     = make_float4(T1[0], T1[1], T1[2], T1[3]); \
            *(float4*)(pA + (2*t + (RR))*SAW + 4) = make_float4(T1[4], T1[5], T1[6], T1[7]); \
        }

        LROW(0, CBa, CRa)
        LROW(1, CBb, CRb)
        #undef LROW

        float cb0 = 0.25f * (((CBa[0] + CBa[1]) + CBb[0]) + CBb[1]) - 128.0f;
        float cb1 = 0.25f * (((CBa[2] + CBa[3]) + CBb[2]) + CBb[3]) - 128.0f;
        float cb2 = 0.25f * (((CBa[4] + CBa[5]) + CBb[4]) + CBb[5]) - 128.0f;
        float cb3 = 0.25f * (((CBa[6] + CBa[7]) + CBb[6]) + CBb[7]) - 128.0f;
        float cr0 = 0.25f * (((CRa[0] + CRa[1]) + CRb[0]) + CRb[1]) - 128.0f;
        float cr1 = 0.25f * (((CRa[2] + CRa[3]) + CRb[2]) + CRb[3]) - 128.0f;
        float cr2 = 0.25f * (((CRa[4] + CRa[5]) + CRb[4]) + CRb[5]) - 128.0f;
        float cr3 = 0.25f * (((CRa[6] + CRa[7]) + CRb[6]) + CRb[7]) - 128.0f;
        *(float4*)&s_c[0][by_*4 + t][bx_*4] = make_float4(cb0, cb1, cb2, cb3);
        *(float4*)&s_c[1][by_*4 + t][bx_*4] = make_float4(cr0, cr1, cr2, cr3);
    }
    __syncthreads();

    // ---- DCT section: 48 units * 4 threads; rows {2r, 2r+1} ----
    const bool act = tid < 192;
    const int unit = tid >> 2;
    const int r    = tid & 3;
    int c, by, bx;
    if (unit < 16) { c = 0; by = unit >> 3; bx = unit & 7; }
    else { int t2 = unit - 16; c = 1 + (t2 >> 4); int rem = t2 & 15; by = rem >> 3; bx = rem & 7; }
    const int ra = 2 * r, rb = 2 * r + 1;
    float* pW = &s_a[c][by*8][bx*8];

    if (act) {
        // ---- stage A (chroma only; luma A' already written in phase 1) ----
        if (c != 0) {
            const float* pC = &s_c[c-1][by*4][bx*4];
            const float4 xh = *(const float4*)(pC + r*SCW);
            float A[8];
            #pragma unroll
            for (int l = 0; l < 8; l++) {
                const float4 d0 = *(const float4*)&c_D[l*8];
                const float4 d1 = *(const float4*)&c_D[l*8 + 4];
                float e0 = d0.x + d0.y, e1 = d0.z + d0.w;
                float e2 = d1.x + d1.y, e3 = d1.z + d1.w;
                A[l] = fmaf(xh.w, e3, fmaf(xh.z, e2, fmaf(xh.y, e1, xh.x * e0)));
            }
            __syncwarp();
            *(float4*)(pW + r*SAW)     = make_float4(A[0], A[1], A[2], A[3]);
            *(float4*)(pW + r*SAW + 4) = make_float4(A[4], A[5], A[6], A[7]);
        }
        __syncwarp();

        // ---- stage 2: F = D * A' (or E * A''), quant/dequant, V = dec * D ----
        float Va[8], Vb[8];
        {
            float Fa[8], Fb[8];
            #pragma unroll
            for (int l = 0; l < 8; l++) { Fa[l] = 0.0f; Fb[l] = 0.0f; }
            if (c == 0) {
                #pragma unroll
                for (int j = 0; j < 8; j++) {
                    const float da = s_d[ra][j];
                    const float db = s_d[rb][j];
                    const float4 a0 = *(const float4*)(pW + j*SAW);
                    const float4 a1 = *(const float4*)(pW + j*SAW + 4);
                    Fa[0] = fmaf(da, a0.x, Fa[0]);  Fb[0] = fmaf(db, a0.x, Fb[0]);
                    Fa[1] = fmaf(da, a0.y, Fa[1]);  Fb[1] = fmaf(db, a0.y, Fb[1]);
                    Fa[2] = fmaf(da, a0.z, Fa[2]);  Fb[2] = fmaf(db, a0.z, Fb[2]);
                    Fa[3] = fmaf(da, a0.w, Fa[3]);  Fb[3] = fmaf(db, a0.w, Fb[3]);
                    Fa[4] = fmaf(da, a1.x, Fa[4]);  Fb[4] = fmaf(db, a1.x, Fb[4]);
                    Fa[5] = fmaf(da, a1.y, Fa[5]);  Fb[5] = fmaf(db, a1.y, Fb[5]);
                    Fa[6] = fmaf(da, a1.z, Fa[6]);  Fb[6] = fmaf(db, a1.z, Fb[6]);
                    Fa[7] = fmaf(da, a1.w, Fa[7]);  Fb[7] = fmaf(db, a1.w, Fb[7]);
                }
            } else {
                #pragma unroll
                for (int m = 0; m < 4; m++) {
                    const float ea = s_e[ra][m];
                    const float eb = s_e[rb][m];
                    const float4 a0 = *(const float4*)(pW + m*SAW);
                    const float4 a1 = *(const float4*)(pW + m*SAW + 4);
                    Fa[0] = fmaf(ea, a0.x, Fa[0]);  Fb[0] = fmaf(eb, a0.x, Fb[0]);
                    Fa[1] = fmaf(ea, a0.y, Fa[1]);  Fb[1] = fmaf(eb, a0.y, Fb[1]);
                    Fa[2] = fmaf(ea, a0.z, Fa[2]);  Fb[2] = fmaf(eb, a0.z, Fb[2]);
                    Fa[3] = fmaf(ea, a0.w, Fa[3]);  Fb[3] = fmaf(eb, a0.w, Fb[3]);
                    Fa[4] = fmaf(ea, a1.x, Fa[4]);  Fb[4] = fmaf(eb, a1.x, Fb[4]);
                    Fa[5] = fmaf(ea, a1.y, Fa[5]);  Fb[5] = fmaf(eb, a1.y, Fb[5]);
                    Fa[6] = fmaf(ea, a1.z, Fa[6]);  Fb[6] = fmaf(eb, a1.z, Fb[6]);
                    Fa[7] = fmaf(ea, a1.w, Fa[7]);  Fb[7] = fmaf(eb, a1.w, Fb[7]);
                }
            }
            {
                const float4 q0  = *(const float4*)&s_q[c][ra][0];
                const float4 q1  = *(const float4*)&s_q[c][ra][4];
                const float4 rq0 = *(const float4*)&s_rq[c][ra][0];
                const float4 rq1 = *(const float4*)&s_rq[c][ra][4];
                Fa[0] = rintf(rintf(Fa[0]*rq0.x)*q0.x);  Fa[1] = rintf(rintf(Fa[1]*rq0.y)*q0.y);
                Fa[2] = rintf(rintf(Fa[2]*rq0.z)*q0.z);  Fa[3] = rintf(rintf(Fa[3]*rq0.w)*q0.w);
                Fa[4] = rintf(rintf(Fa[4]*rq1.x)*q1.x);  Fa[5] = rintf(rintf(Fa[5]*rq1.y)*q1.y);
                Fa[6] = rintf(rintf(Fa[6]*rq1.z)*q1.z);  Fa[7] = rintf(rintf(Fa[7]*rq1.w)*q1.w);
            }
            {
                const float4 q0  = *(const float4*)&s_q[c][rb][0];
                const float4 q1  = *(const float4*)&s_q[c][rb][4];
                const float4 rq0 = *(const float4*)&s_rq[c][rb][0];
                const float4 rq1 = *(const float4*)&s_rq[c][rb][4];
                Fb[0] = rintf(rintf(Fb[0]*rq0.x)*q0.x);  Fb[1] = rintf(rintf(Fb[1]*rq0.y)*q0.y);
                Fb[2] = rintf(rintf(Fb[2]*rq0.z)*q0.z);  Fb[3] = rintf(rintf(Fb[3]*rq0.w)*q0.w);
                Fb[4] = rintf(rintf(Fb[4]*rq1.x)*q1.x);  Fb[5] = rintf(rintf(Fb[5]*rq1.y)*q1.y);
                Fb[6] = rintf(rintf(Fb[6]*rq1.z)*q1.z);  Fb[7] = rintf(rintf(Fb[7]*rq1.w)*q1.w);
            }
            #pragma unroll
            for (int l = 0; l < 8; l++) { Va[l] = 0.0f; Vb[l] = 0.0f; }
            #pragma unroll
            for (int k = 0; k < 8; k++) {
                const float4 d0 = *(const float4*)&c_D[k*8];
                const float4 d1 = *(const float4*)&c_D[k*8 + 4];
                const float ta = Fa[k], tb = Fb[k];
                Va[0] = fmaf(ta, d0.x, Va[0]);  Vb[0] = fmaf(tb, d0.x, Vb[0]);
                Va[1] = fmaf(ta, d0.y, Va[1]);  Vb[1] = fmaf(tb, d0.y, Vb[1]);
                Va[2] = fmaf(ta, d0.z, Va[2]);  Vb[2] = fmaf(tb, d0.z, Vb[2]);
                Va[3] = fmaf(ta, d0.w, Va[3]);  Vb[3] = fmaf(tb, d0.w, Vb[3]);
                Va[4] = fmaf(ta, d1.x, Va[4]);  Vb[4] = fmaf(tb, d1.x, Vb[4]);
                Va[5] = fmaf(ta, d1.y, Va[5]);  Vb[5] = fmaf(tb, d1.y, Vb[5]);
                Va[6] = fmaf(ta, d1.z, Va[6]);  Vb[6] = fmaf(tb, d1.z, Vb[6]);
                Va[7] = fmaf(ta, d1.w, Va[7]);  Vb[7] = fmaf(tb, d1.w, Vb[7]);
            }
        }
        __syncwarp();
        *(float4*)(pW + ra*SAW)     = make_float4(Va[0], Va[1], Va[2], Va[3]);
        *(float4*)(pW + ra*SAW + 4) = make_float4(Va[4], Va[5], Va[6], Va[7]);
        *(float4*)(pW + rb*SAW)     = make_float4(Vb[0], Vb[1], Vb[2], Vb[3]);
        *(float4*)(pW + rb*SAW + 4) = make_float4(Vb[4], Vb[5], Vb[6], Vb[7]);
        __syncwarp();

        // ---- stage 3: Z = D^T * V ----
        float zA[8], zB[8];
        #pragma unroll
        for (int l = 0; l < 8; l++) { zA[l] = 0.0f; zB[l] = 0.0f; }
        #pragma unroll
        for (int j = 0; j < 8; j++) {
            const float da = s_dt[ra][j];
            const float db = s_dt[rb][j];
            const float4 v0 = *(const float4*)(pW + j*SAW);
            const float4 v1 = *(const float4*)(pW + j*SAW + 4);
            zA[0] = fmaf(da, v0.x, zA[0]);  zB[0] = fmaf(db, v0.x, zB[0]);
            zA[1] = fmaf(da, v0.y, zA[1]);  zB[1] = fmaf(db, v0.y, zB[1]);
            zA[2] = fmaf(da, v0.z, zA[2]);  zB[2] = fmaf(db, v0.z, zB[2]);
            zA[3] = fmaf(da, v0.w, zA[3]);  zB[3] = fmaf(db, v0.w, zB[3]);
            zA[4] = fmaf(da, v1.x, zA[4]);  zB[4] = fmaf(db, v1.x, zB[4]);
            zA[5] = fmaf(da, v1.y, zA[5]);  zB[5] = fmaf(db, v1.y, zB[5]);
            zA[6] = fmaf(da, v1.z, zA[6]);  zB[6] = fmaf(db, v1.z, zB[6]);
            zA[7] = fmaf(da, v1.w, zA[7]);  zB[7] = fmaf(db, v1.w, zB[7]);
        }
        const float off = (c == 0) ? 128.0f : 0.0f;
        #pragma unroll
        for (int l = 0; l < 8; l++) { zA[l] += off; zB[l] += off; }
        __syncwarp();
        *(float4*)(pW + ra*SAW)     = make_float4(zA[0], zA[1], zA[2], zA[3]);
        *(float4*)(pW + ra*SAW + 4) = make_float4(zA[4], zA[5], zA[6], zA[7]);
        *(float4*)(pW + rb*SAW)     = make_float4(zB[0], zB[1], zB[2], zB[3]);
        *(float4*)(pW + rb*SAW + 4) = make_float4(zB[4], zB[5], zB[6], zB[7]);
    }
    __syncthreads();

    // ---- phase 5: YCbCr -> RGB, clip, round, store ----
    {
        const int py  = tid >> 4;
        const int px4 = (tid & 15) * 4;
        const float4 yv  = *(const float4*)&s_a[0][py][px4];
        const float4 cbv = *(const float4*)&s_a[1][py][px4];
        const float4 crv = *(const float4*)&s_a[2][py][px4];

        #define FIN(v) (rintf(fminf(fmaxf((v), 0.0f), 255.0f)) * (1.0f/255.0f))
        float4 R, G, Bv;
        R.x = FIN(fmaf(1.402f, crv.x, yv.x));  R.y = FIN(fmaf(1.402f, crv.y, yv.y));
        R.z = FIN(fmaf(1.402f, crv.z, yv.z));  R.w = FIN(fmaf(1.402f, crv.w, yv.w));
        G.x = FIN(fmaf(-0.714136286f, crv.x, fmaf(-0.344136286f, cbv.x, yv.x)));
        G.y = FIN(fmaf(-0.714136286f, crv.y, fmaf(-0.344136286f, cbv.y, yv.y)));
        G.z = FIN(fmaf(-0.714136286f, crv.z, fmaf(-0.344136286f, cbv.z, yv.z)));
        G.w = FIN(fmaf(-0.714136286f, crv.w, fmaf(-0.344136286f, cbv.w, yv.w)));
        Bv.x = FIN(fmaf(1.772f, cbv.x, yv.x)); Bv.y = FIN(fmaf(1.772f, cbv.y, yv.y));
        Bv.z = FIN(fmaf(1.772f, cbv.z, yv.z)); Bv.w = FIN(fmaf(1.772f, cbv.w, yv.w));

        const size_t idx = (size_t)(ty0 + py) * WIMG + (tx0 + px4);
        *(float4*)&obase[idx]           = R;
        *(float4*)&obase[plane + idx]   = G;
        *(float4*)&obase[2*plane + idx] = Bv;
    }
}

extern "C" void kernel_launch(void* const* d_in, const int* in_sizes, int n_in,
                              void* d_out, int out_size)
{
    const float* x = nullptr;
    const float* q = nullptr;
    const float* d = nullptr;
    int nimg = 0;
    for (int i = 0; i < n_in; i++) {
        if (in_sizes[i] == 192)      q = (const float*)d_in[i];
        else if (in_sizes[i] == 64)  d = (const float*)d_in[i];
        else { x = (const float*)d_in[i]; nimg = in_sizes[i] / (3 * HIMG * WIMG); }
    }
    cudaMemcpyToSymbolAsync(c_D, d, 64 * sizeof(float), 0,
                            cudaMemcpyDeviceToDevice, 0);
    dim3 grid(WIMG / TW, HIMG / TH, nimg);
    jpeg_kernel<<<grid, NT>>>(x, q, d, (float*)d_out);
}

// round 14
// speedup vs baseline: 2.0548x; 1.3669x over previous
#include <cuda_runtime.h>

#define TH 16
#define TW 64
#define NT 256
#define HIMG 512
#define WIMG 512
#define SAW 68   // padded row stride for s_a
#define SCW 36   // padded row stride for s_c (half-res chroma)

__constant__ float c_D[64];   // DCT matrix, row-major

__global__ __launch_bounds__(NT, 5) void jpeg_kernel(
    const float* __restrict__ in, const float* __restrict__ quant,
    const float* __restrict__ dct, float* __restrict__ out)
{
    __shared__ __align__(16) float s_a[3][TH][SAW];   // y / A' / V / Z
    __shared__ __align__(16) float s_c[2][TH/2][SCW]; // half-res chroma
    __shared__ __align__(16) float s_d[8][8];         // D (lane-varying reads)
    __shared__ __align__(16) float s_dt[8][8];        // D^T
    __shared__ __align__(16) float s_e[8][4];         // E
    __shared__ __align__(16) float s_q[3][8][8];
    __shared__ __align__(16) float s_rq[3][8][8];

    const int tid = threadIdx.x;
    const int b   = blockIdx.z;
    const int ty0 = blockIdx.y * TH;
    const int tx0 = blockIdx.x * TW;

    const size_t plane = (size_t)HIMG * WIMG;
    const float* base  = in  + (size_t)b * 3 * plane;
    float*       obase = out + (size_t)b * 3 * plane;

    // ---- phase-1 global loads issued FIRST (overlap table setup with DRAM) ----
    const int sy = tid >> 4;                 // 0..15 (row)
    const int sx = tid & 15;                 // 0..15 (strip)
    const int px = sx * 4;
    const size_t gidx = (size_t)(ty0 + sy) * WIMG + (tx0 + px);
    const float4 r4 = __ldg((const float4*)&base[gidx]);
    const float4 g4 = __ldg((const float4*)&base[plane + gidx]);
    const float4 b4 = __ldg((const float4*)&base[2*plane + gidx]);

    // ---- tables (overlapped with load latency) ----
    if (tid < 64) {
        float v = dct[tid];
        int i = tid >> 3, j = tid & 7;
        s_d[i][j]  = v;
        s_dt[j][i] = v;
    }
    if (tid < 32) {
        int i = tid >> 2, h = tid & 3;
        s_e[i][h] = dct[i * 8 + 2 * h] + dct[i * 8 + 2 * h + 1];
    }
    if (tid >= 64) {
        int i = tid - 64;
        float qv = rintf(quant[i] * 255.0f);
        float q1 = rintf((qv * 50.0f + 50.0f) / 100.0f);
        float q  = fminf(fmaxf(q1, 1.0f), 255.0f);
        int ci = i >> 6, ri = (i >> 3) & 7, li = i & 7;
        s_q[ci][ri][li]  = q;
        s_rq[ci][ri][li] = 1.0f / q;
    }

    // ---- phase 1: color transform; chroma 2x2 mean via in-warp shuffle ----
    {
        float R[4] = {255.0f*r4.x, 255.0f*r4.y, 255.0f*r4.z, 255.0f*r4.w};
        float G[4] = {255.0f*g4.x, 255.0f*g4.y, 255.0f*g4.z, 255.0f*g4.w};
        float B[4] = {255.0f*b4.x, 255.0f*b4.y, 255.0f*b4.z, 255.0f*b4.w};

        #define YV(R_,G_,B_)  fmaf(0.114f,(B_), fmaf(0.587f,(G_), 0.299f*(R_)))
        #define CBV(R_,G_,B_) (fmaf(0.5f,(B_),  fmaf(-0.331264108f,(G_), -0.168735892f*(R_))) + 128.0f)
        #define CRV(R_,G_,B_) (fmaf(-0.081312411f,(B_), fmaf(-0.418687589f,(G_), 0.5f*(R_))) + 128.0f)
        #define CL(v) fminf(fmaxf((v), 0.0f), 255.0f)

        float Y[4], CB[4], CR[4];
        #pragma unroll
        for (int e = 0; e < 4; e++) {
            Y[e]  = CL(YV(R[e], G[e], B[e])) - 128.0f;
            CB[e] = CL(CBV(R[e], G[e], B[e]));
            CR[e] = CL(CRV(R[e], G[e], B[e]));
        }
        *(float4*)&s_a[0][sy][px] = make_float4(Y[0], Y[1], Y[2], Y[3]);

        // partner = adjacent row (tid^16, same warp). Even row computes means.
        float pcb0 = __shfl_xor_sync(0xffffffffu, CB[0], 16);
        float pcb1 = __shfl_xor_sync(0xffffffffu, CB[1], 16);
        float pcb2 = __shfl_xor_sync(0xffffffffu, CB[2], 16);
        float pcb3 = __shfl_xor_sync(0xffffffffu, CB[3], 16);
        float pcr0 = __shfl_xor_sync(0xffffffffu, CR[0], 16);
        float pcr1 = __shfl_xor_sync(0xffffffffu, CR[1], 16);
        float pcr2 = __shfl_xor_sync(0xffffffffu, CR[2], 16);
        float pcr3 = __shfl_xor_sync(0xffffffffu, CR[3], 16);
        if ((sy & 1) == 0) {
            float cbm0 = 0.25f * (((CB[0] + CB[1]) + pcb0) + pcb1) - 128.0f;
            float cbm1 = 0.25f * (((CB[2] + CB[3]) + pcb2) + pcb3) - 128.0f;
            float crm0 = 0.25f * (((CR[0] + CR[1]) + pcr0) + pcr1) - 128.0f;
            float crm1 = 0.25f * (((CR[2] + CR[3]) + pcr2) + pcr3) - 128.0f;
            *(float2*)&s_c[0][sy >> 1][sx*2] = make_float2(cbm0, cbm1);
            *(float2*)&s_c[1][sy >> 1][sx*2] = make_float2(crm0, crm1);
        }
    }
    __syncthreads();

    // ---- assignment: 48 units * 4 threads (rows r and r+4); unit = warp-quad ----
    const bool act = tid < 192;
    const int unit = tid >> 2;    // 0..47
    const int r    = tid & 3;
    int c, by, bx;
    if (unit < 16) { c = 0; by = unit >> 3; bx = unit & 7; }
    else { int t = unit - 16; c = 1 + (t >> 4); int rem = t & 15; by = rem >> 3; bx = rem & 7; }
    const int ra = r, rb = r + 4;
    float* pW = &s_a[c][by*8][bx*8];

    if (act) {
        // ---- stage 1: A' = X * D^T (row-local; uniform const coeffs) ----
        if (c == 0) {
            #pragma unroll
            for (int pass = 0; pass < 2; pass++) {
                const int rr = pass ? rb : ra;
                const float4 x0 = *(const float4*)(pW + rr*SAW);
                const float4 x1 = *(const float4*)(pW + rr*SAW + 4);
                float A[8];
                #pragma unroll
                for (int l = 0; l < 8; l++) {
                    const float4 d0 = *(const float4*)&c_D[l*8];
                    const float4 d1 = *(const float4*)&c_D[l*8 + 4];
                    A[l] = fmaf(x1.w, d1.w, fmaf(x1.z, d1.z, fmaf(x1.y, d1.y,
                           fmaf(x1.x, d1.x, fmaf(x0.w, d0.w, fmaf(x0.z, d0.z,
                           fmaf(x0.y, d0.y, x0.x * d0.x)))))));
                }
                *(float4*)(pW + rr*SAW)     = make_float4(A[0], A[1], A[2], A[3]);
                *(float4*)(pW + rr*SAW + 4) = make_float4(A[4], A[5], A[6], A[7]);
            }
        } else {
            const float* pC = &s_c[c-1][by*4][bx*4];
            const float4 xh = *(const float4*)(pC + r*SCW);
            float A[8];
            #pragma unroll
            for (int l = 0; l < 8; l++) {
                const float4 d0 = *(const float4*)&c_D[l*8];
                const float4 d1 = *(const float4*)&c_D[l*8 + 4];
                float e0 = d0.x + d0.y, e1 = d0.z + d0.w;
                float e2 = d1.x + d1.y, e3 = d1.z + d1.w;
                A[l] = fmaf(xh.w, e3, fmaf(xh.z, e2, fmaf(xh.y, e1, xh.x * e0)));
            }
            *(float4*)(pW + r*SAW)     = make_float4(A[0], A[1], A[2], A[3]);
            *(float4*)(pW + r*SAW + 4) = make_float4(A[4], A[5], A[6], A[7]);
        }
        __syncwarp();   // unit (4 threads) is warp-local: A' visible

        // ---- stage 2: F = D * A' (transpose), quant/dequant, V = dec * D ----
        float Va[8], Vb[8];
        {
            float Fa[8], Fb[8];
            #pragma unroll
            for (int l = 0; l < 8; l++) { Fa[l] = 0.0f; Fb[l] = 0.0f; }
            if (c == 0) {
                #pragma unroll
                for (int j = 0; j < 8; j++) {
                    const float da = s_d[ra][j];
                    const float db = s_d[rb][j];
                    const float4 a0 = *(const float4*)(pW + j*SAW);
                    const float4 a1 = *(const float4*)(pW + j*SAW + 4);
                    Fa[0] = fmaf(da, a0.x, Fa[0]);  Fb[0] = fmaf(db, a0.x, Fb[0]);
                    Fa[1] = fmaf(da, a0.y, Fa[1]);  Fb[1] = fmaf(db, a0.y, Fb[1]);
                    Fa[2] = fmaf(da, a0.z, Fa[2]);  Fb[2] = fmaf(db, a0.z, Fb[2]);
                    Fa[3] = fmaf(da, a0.w, Fa[3]);  Fb[3] = fmaf(db, a0.w, Fb[3]);
                    Fa[4] = fmaf(da, a1.x, Fa[4]);  Fb[4] = fmaf(db, a1.x, Fb[4]);
                    Fa[5] = fmaf(da, a1.y, Fa[5]);  Fb[5] = fmaf(db, a1.y, Fb[5]);
                    Fa[6] = fmaf(da, a1.z, Fa[6]);  Fb[6] = fmaf(db, a1.z, Fb[6]);
                    Fa[7] = fmaf(da, a1.w, Fa[7]);  Fb[7] = fmaf(db, a1.w, Fb[7]);
                }
            } else {
                #pragma unroll
                for (int m = 0; m < 4; m++) {
                    const float ea = s_e[ra][m];
                    const float eb = s_e[rb][m];
                    const float4 a0 = *(const float4*)(pW + m*SAW);
                    const float4 a1 = *(const float4*)(pW + m*SAW + 4);
                    Fa[0] = fmaf(ea, a0.x, Fa[0]);  Fb[0] = fmaf(eb, a0.x, Fb[0]);
                    Fa[1] = fmaf(ea, a0.y, Fa[1]);  Fb[1] = fmaf(eb, a0.y, Fb[1]);
                    Fa[2] = fmaf(ea, a0.z, Fa[2]);  Fb[2] = fmaf(eb, a0.z, Fb[2]);
                    Fa[3] = fmaf(ea, a0.w, Fa[3]);  Fb[3] = fmaf(eb, a0.w, Fb[3]);
                    Fa[4] = fmaf(ea, a1.x, Fa[4]);  Fb[4] = fmaf(eb, a1.x, Fb[4]);
                    Fa[5] = fmaf(ea, a1.y, Fa[5]);  Fb[5] = fmaf(eb, a1.y, Fb[5]);
                    Fa[6] = fmaf(ea, a1.z, Fa[6]);  Fb[6] = fmaf(eb, a1.z, Fb[6]);
                    Fa[7] = fmaf(ea, a1.w, Fa[7]);  Fb[7] = fmaf(eb, a1.w, Fb[7]);
                }
            }
            {
                const float4 q0  = *(const float4*)&s_q[c][ra][0];
                const float4 q1  = *(const float4*)&s_q[c][ra][4];
                const float4 rq0 = *(const float4*)&s_rq[c][ra][0];
                const float4 rq1 = *(const float4*)&s_rq[c][ra][4];
                Fa[0] = rintf(rintf(Fa[0]*rq0.x)*q0.x);  Fa[1] = rintf(rintf(Fa[1]*rq0.y)*q0.y);
                Fa[2] = rintf(rintf(Fa[2]*rq0.z)*q0.z);  Fa[3] = rintf(rintf(Fa[3]*rq0.w)*q0.w);
                Fa[4] = rintf(rintf(Fa[4]*rq1.x)*q1.x);  Fa[5] = rintf(rintf(Fa[5]*rq1.y)*q1.y);
                Fa[6] = rintf(rintf(Fa[6]*rq1.z)*q1.z);  Fa[7] = rintf(rintf(Fa[7]*rq1.w)*q1.w);
            }
            {
                const float4 q0  = *(const float4*)&s_q[c][rb][0];
                const float4 q1  = *(const float4*)&s_q[c][rb][4];
                const float4 rq0 = *(const float4*)&s_rq[c][rb][0];
                const float4 rq1 = *(const float4*)&s_rq[c][rb][4];
                Fb[0] = rintf(rintf(Fb[0]*rq0.x)*q0.x);  Fb[1] = rintf(rintf(Fb[1]*rq0.y)*q0.y);
                Fb[2] = rintf(rintf(Fb[2]*rq0.z)*q0.z);  Fb[3] = rintf(rintf(Fb[3]*rq0.w)*q0.w);
                Fb[4] = rintf(rintf(Fb[4]*rq1.x)*q1.x);  Fb[5] = rintf(rintf(Fb[5]*rq1.y)*q1.y);
                Fb[6] = rintf(rintf(Fb[6]*rq1.z)*q1.z);  Fb[7] = rintf(rintf(Fb[7]*rq1.w)*q1.w);
            }
            #pragma unroll
            for (int l = 0; l < 8; l++) { Va[l] = 0.0f; Vb[l] = 0.0f; }
            #pragma unroll
            for (int k = 0; k < 8; k++) {
                const float4 d0 = *(const float4*)&c_D[k*8];
                const float4 d1 = *(const float4*)&c_D[k*8 + 4];
                const float ta = Fa[k], tb = Fb[k];
                Va[0] = fmaf(ta, d0.x, Va[0]);  Vb[0] = fmaf(tb, d0.x, Vb[0]);
                Va[1] = fmaf(ta, d0.y, Va[1]);  Vb[1] = fmaf(tb, d0.y, Vb[1]);
                Va[2] = fmaf(ta, d0.z, Va[2]);  Vb[2] = fmaf(tb, d0.z, Vb[2]);
                Va[3] = fmaf(ta, d0.w, Va[3]);  Vb[3] = fmaf(tb, d0.w, Vb[3]);
                Va[4] = fmaf(ta, d1.x, Va[4]);  Vb[4] = fmaf(tb, d1.x, Vb[4]);
                Va[5] = fmaf(ta, d1.y, Va[5]);  Vb[5] = fmaf(tb, d1.y, Vb[5]);
                Va[6] = fmaf(ta, d1.z, Va[6]);  Vb[6] = fmaf(tb, d1.z, Vb[6]);
                Va[7] = fmaf(ta, d1.w, Va[7]);  Vb[7] = fmaf(tb, d1.w, Vb[7]);
            }
        }
        __syncwarp();   // all A' reads in unit done -> safe to overwrite
        *(float4*)(pW + ra*SAW)     = make_float4(Va[0], Va[1], Va[2], Va[3]);
        *(float4*)(pW + ra*SAW + 4) = make_float4(Va[4], Va[5], Va[6], Va[7]);
        *(float4*)(pW + rb*SAW)     = make_float4(Vb[0], Vb[1], Vb[2], Vb[3]);
        *(float4*)(pW + rb*SAW + 4) = make_float4(Vb[4], Vb[5], Vb[6], Vb[7]);
        __syncwarp();   // V visible within unit

        // ---- stage 3: Z = D^T * V (transpose) ----
        float zA[8], zB[8];
        #pragma unroll
        for (int l = 0; l < 8; l++) { zA[l] = 0.0f; zB[l] = 0.0f; }
        #pragma unroll
        for (int j = 0; j < 8; j++) {
            const float da = s_dt[ra][j];
            const float db = s_dt[rb][j];
            const float4 v0 = *(const float4*)(pW + j*SAW);
            const float4 v1 = *(const float4*)(pW + j*SAW + 4);
            zA[0] = fmaf(da, v0.x, zA[0]);  zB[0] = fmaf(db, v0.x, zB[0]);
            zA[1] = fmaf(da, v0.y, zA[1]);  zB[1] = fmaf(db, v0.y, zB[1]);
            zA[2] = fmaf(da, v0.z, zA[2]);  zB[2] = fmaf(db, v0.z, zB[2]);
            zA[3] = fmaf(da, v0.w, zA[3]);  zB[3] = fmaf(db, v0.w, zB[3]);
            zA[4] = fmaf(da, v1.x, zA[4]);  zB[4] = fmaf(db, v1.x, zB[4]);
            zA[5] = fmaf(da, v1.y, zA[5]);  zB[5] = fmaf(db, v1.y, zB[5]);
            zA[6] = fmaf(da, v1.z, zA[6]);  zB[6] = fmaf(db, v1.z, zB[6]);
            zA[7] = fmaf(da, v1.w, zA[7]);  zB[7] = fmaf(db, v1.w, zB[7]);
        }
        const float off = (c == 0) ? 128.0f : 0.0f;
        #pragma unroll
        for (int l = 0; l < 8; l++) { zA[l] += off; zB[l] += off; }
        __syncwarp();   // all V reads in unit done -> safe to overwrite
        *(float4*)(pW + ra*SAW)     = make_float4(zA[0], zA[1], zA[2], zA[3]);
        *(float4*)(pW + ra*SAW + 4) = make_float4(zA[4], zA[5], zA[6], zA[7]);
        *(float4*)(pW + rb*SAW)     = make_float4(zB[0], zB[1], zB[2], zB[3]);
        *(float4*)(pW + rb*SAW + 4) = make_float4(zB[4], zB[5], zB[6], zB[7]);
    }
    __syncthreads();

    // ---- phase 5: YCbCr -> RGB, clip, round, store ----
    {
        const int py  = tid >> 4;
        const int px4 = (tid & 15) * 4;
        const float4 yv  = *(const float4*)&s_a[0][py][px4];
        const float4 cbv = *(const float4*)&s_a[1][py][px4];
        const float4 crv = *(const float4*)&s_a[2][py][px4];

        #define FIN(v) (rintf(fminf(fmaxf((v), 0.0f), 255.0f)) * (1.0f/255.0f))
        float4 R, G, Bv;
        R.x = FIN(fmaf(1.402f, crv.x, yv.x));  R.y = FIN(fmaf(1.402f, crv.y, yv.y));
        R.z = FIN(fmaf(1.402f, crv.z, yv.z));  R.w = FIN(fmaf(1.402f, crv.w, yv.w));
        G.x = FIN(fmaf(-0.714136286f, crv.x, fmaf(-0.344136286f, cbv.x, yv.x)));
        G.y = FIN(fmaf(-0.714136286f, crv.y, fmaf(-0.344136286f, cbv.y, yv.y)));
        G.z = FIN(fmaf(-0.714136286f, crv.z, fmaf(-0.344136286f, cbv.z, yv.z)));
        G.w = FIN(fmaf(-0.714136286f, crv.w, fmaf(-0.344136286f, cbv.w, yv.w)));
        Bv.x = FIN(fmaf(1.772f, cbv.x, yv.x)); Bv.y = FIN(fmaf(1.772f, cbv.y, yv.y));
        Bv.z = FIN(fmaf(1.772f, cbv.z, yv.z)); Bv.w = FIN(fmaf(1.772f, cbv.w, yv.w));

        const size_t idx = (size_t)(ty0 + py) * WIMG + (tx0 + px4);
        *(float4*)&obase[idx]           = R;
        *(float4*)&obase[plane + idx]   = G;
        *(float4*)&obase[2*plane + idx] = Bv;
    }
}

extern "C" void kernel_launch(void* const* d_in, const int* in_sizes, int n_in,
                              void* d_out, int out_size)
{
    const float* x = nullptr;
    const float* q = nullptr;
    const float* d = nullptr;
    int nimg = 0;
    for (int i = 0; i < n_in; i++) {
        if (in_sizes[i] == 192)      q = (const float*)d_in[i];
        else if (in_sizes[i] == 64)  d = (const float*)d_in[i];
        else { x = (const float*)d_in[i]; nimg = in_sizes[i] / (3 * HIMG * WIMG); }
    }
    cudaMemcpyToSymbolAsync(c_D, d, 64 * sizeof(float), 0,
                            cudaMemcpyDeviceToDevice, 0);
    dim3 grid(WIMG / TW, HIMG / TH, nimg);
    jpeg_kernel<<<grid, NT>>>(x, q, d, (float*)d_out);
}